// round 15
// baseline (speedup 1.0000x reference)
#include <cuda_runtime.h>
#include <cstdint>
#include <math_constants.h>

// Problem constants
#define BATCH 64
#define M     4096   // NPROP (columns)
#define NGTC  128    // max GT (rows)
#define NT    512    // threads per CTA (assign kernel)
#define CPT   (M/NT) // 8 columns per thread
#define NW    (NT/32)// 16 warps
#define LOGNT 9      // log2(NT)

// rowmin kernel config
#define K1NT   256
#define K1CPT  (M/K1NT)  // 16
#define K1NW   (K1NT/32) // 8
#define RT     8         // rows per tile
#define NTILES (NGTC/RT) // 16

#define FREEROW 0x7FFFFFFF

// Order-preserving float <-> uint32
__device__ __forceinline__ unsigned f2o(float f) {
    unsigned x = __float_as_uint(f);
    return x ^ ((x & 0x80000000u) ? 0xFFFFFFFFu : 0x80000000u);
}
__device__ __forceinline__ float o2f(unsigned x) {
    unsigned w = (x & 0x80000000u) ? (x ^ 0x80000000u) : ~x;
    return __uint_as_float(w);
}
// Order-preserving double <-> uint64
__device__ __forceinline__ unsigned long long ord64(double x) {
    long long s = __double_as_longlong(x);
    return (unsigned long long)s ^ ((unsigned long long)(s >> 63) | 0x8000000000000000ull);
}
__device__ __forceinline__ double unord64(unsigned long long k) {
    long long b = (k & 0x8000000000000000ull) ? (long long)(k ^ 0x8000000000000000ull)
                                              : (long long)(~k);
    return __longlong_as_double(b);
}

// Scratch: per-(batch,row) packed (ord32 cost << 32) | argmin column (1-based)
__device__ unsigned long long g_rowkey[BATCH][NGTC];

// ============================================================================
// Kernel 1: chip-wide per-row argmin.  grid (BATCH, NTILES), block K1NT.
// 8 rows kept live simultaneously in the inner loop -> 8 independent
// cmp/sel dependency chains (latency hidden), vs serial per-row chains.
// ============================================================================
__global__ __launch_bounds__(K1NT)
void rowmin_kernel(const int*   __restrict__ nag,
                   const float* __restrict__ gtn,   // [B][NGT][3]
                   const float* __restrict__ qn)    // [M][3]
{
    const int b    = blockIdx.x;
    const int base = blockIdx.y * RT;               // 0-based first row of tile
    const int k    = nag[b];
    if (base >= k) return;
    const int nr   = min(RT, k - base);

    const int tid  = threadIdx.x;
    const int lane = tid & 31;
    const int wid  = tid >> 5;

    __shared__ unsigned long long awk[RT][K1NW];

    // gt normals for all 8 tile rows (rows >= k are garbage but harmless:
    // gtn is allocated/normalized for all NGTC rows; results unwritten)
    float gx[RT], gy[RT], gz[RT];
    #pragma unroll
    for (int r = 0; r < RT; r++) {
        gx[r] = gtn[((size_t)b * NGTC + base + r) * 3 + 0];
        gy[r] = gtn[((size_t)b * NGTC + base + r) * 3 + 1];
        gz[r] = gtn[((size_t)b * NGTC + base + r) * 3 + 2];
    }

    float bcr[RT]; int bjr[RT];
    #pragma unroll
    for (int r = 0; r < RT; r++) { bcr[r] = CUDART_INF_F; bjr[r] = M; }

    #pragma unroll
    for (int t = 0; t < K1CPT; t++) {
        int c = tid + t * K1NT;
        const float qx = qn[c * 3 + 0];
        const float qy = qn[c * 3 + 1];
        const float qz = qn[c * 3 + 2];
        const int   j  = c + 1;
        #pragma unroll
        for (int r = 0; r < RT; r++) {
            float dot = fmaf(qz, gz[r], fmaf(qy, gy[r], qx * gx[r]));
            float cf  = 1.0f - dot;                 // matches reference C bit-for-bit
            if (cf < bcr[r]) { bcr[r] = cf; bjr[r] = j; }  // first-min => smallest j
        }
    }

    #pragma unroll
    for (int r = 0; r < RT; r++) {
        unsigned long long kk = ((unsigned long long)f2o(bcr[r]) << 32) | (unsigned)bjr[r];
        #pragma unroll
        for (int off = 16; off; off >>= 1) {
            unsigned long long ok = __shfl_xor_sync(0xFFFFFFFFu, kk, off);
            if (ok < kk) kk = ok;                   // min cost, then min j
        }
        if (lane == 0) awk[r][wid] = kk;
    }
    __syncthreads();
    if (wid < nr) {                                 // warp w finishes row w
        unsigned long long kk = awk[wid][lane & 7];
        #pragma unroll
        for (int off = 4; off; off >>= 1) {
            unsigned long long ok = __shfl_xor_sync(0xFFFFFFFFu, kk, off);
            if (ok < kk) kk = ok;
        }
        if (lane == 0) g_rowkey[b][base + wid] = kk;
    }
}

// ============================================================================
// Kernel 2: greedy claim + JV phases for collisions + outputs. grid BATCH.
// ============================================================================
__global__ __launch_bounds__(NT, 1)
void assign_kernel(const int*   __restrict__ nag,
                   const float* __restrict__ gtn,
                   const float* __restrict__ qn,
                   float*       __restrict__ out)   // [2][B][M] : inds then mask
{
    const int b    = blockIdx.x;
    const int tid  = threadIdx.x;
    const int lane = tid & 31;
    const int wid  = tid >> 5;

    __shared__ int                p[M + 1];        // column -> row (1-based), FREEROW = free
    __shared__ unsigned short     way[M + 1];
    __shared__ double             u[NGTC + 1];
    __shared__ float              gns[NGTC * 3];
    __shared__ unsigned long long rk[NGTC];        // cached row keys
    __shared__ unsigned long long wkey[2][NW];
    __shared__ int                wjj[2][NW];
    __shared__ short              plist[NGTC];
    __shared__ int                wcnt[4];         // pending counts per claim-warp
    __shared__ int                npend;

    const int k = nag[b];

    for (int j = tid; j <= M; j += NT) p[j] = FREEROW;
    for (int j = tid; j < k * 3; j += NT) gns[j] = gtn[(size_t)b * NGTC * 3 + j];
    for (int idx = tid; idx < k; idx += NT) rk[idx] = g_rowkey[b][idx];
    __syncthreads();

    // ---- parallel greedy claim: atomicMin writes winner row directly into p ----
    if (tid < k) {
        int j = (int)(rk[tid] & 0xFFFFFFFFull);
        u[tid + 1] = (double)o2f((unsigned)(rk[tid] >> 32));  // row dual = row min
        atomicMin(&p[j], tid + 1);
    }
    __syncthreads();

    // ---- parallel pending-list build (ascending row order) ----
    if (tid < NGTC) {   // 4 warps participate
        bool pend = false;
        if (tid < k) {
            int j = (int)(rk[tid] & 0xFFFFFFFFull);
            pend = (p[j] != tid + 1);                 // lost the claim
        }
        unsigned m  = __ballot_sync(0xFFFFFFFFu, pend);
        if (lane == 0) wcnt[wid] = __popc(m);
        __syncwarp();
        if (pend) {
            int rank = __popc(m & ((1u << lane) - 1u));
            plist[wid * 32 + rank] = (short)(tid + 1);  // staged per-warp compact
        }
    }
    __syncthreads();
    if (tid == 0) {           // compact staged segments into final ascending list
        int np = 0;
        #pragma unroll
        for (int w = 0; w < 4; w++) {
            int c = wcnt[w];
            for (int r = 0; r < c; r++) plist[np + r] = plist[w * 32 + r];
            np += c;
        }
        npend = np;
    }
    __syncthreads();

    const int np = npend;

    if (np > 0) {
        float q0[CPT], q1[CPT], q2[CPT];
        #pragma unroll
        for (int t = 0; t < CPT; t++) {
            int c = tid + t * NT;
            q0[t] = qn[c * 3 + 0];
            q1[t] = qn[c * 3 + 1];
            q2[t] = qn[c * 3 + 2];
        }

        const double DINF = 1e300;
        double v[CPT], d[CPT];
        int    wreg[CPT];               // per-column 'way' kept in registers
        #pragma unroll
        for (int t = 0; t < CPT; t++) v[t] = 0.0;

        int par = 0;

        for (int pi = 0; pi < np; pi++) {
            const int i = plist[pi];
            unsigned usedmask = 0;
            #pragma unroll
            for (int t = 0; t < CPT; t++) { d[t] = DINF; wreg[t] = 0; }

            int    i0 = i, j0 = 0, jend = 0;
            double minVal = 0.0;

            while (true) {
                const double h1 = minVal - u[i0] + 1.0;  // folds the "1 - dot" constant
                const float  gx = gns[(i0 - 1) * 3 + 0];
                const float  gy = gns[(i0 - 1) * 3 + 1];
                const float  gz = gns[(i0 - 1) * 3 + 2];

                // relax free columns (exact f64); local argmin, smallest j on ties;
                // 'way' stays in registers (no smem stores on the hot path)
                double best  = DINF;
                int    bestj = M + 1;
                #pragma unroll
                for (int t = 0; t < CPT; t++) {
                    if (!((usedmask >> t) & 1u)) {
                        float dot = fmaf(q2[t], gz, fmaf(q1[t], gy, q0[t] * gx));
                        double r  = (h1 - v[t]) - (double)dot;
                        if (r < d[t]) { d[t] = r; wreg[t] = j0; }
                        if (d[t] < best) { best = d[t]; bestj = tid + t * NT + 1; }
                    }
                }

                // stage 1: warp butterfly on (ord64 key, j) — int compares only
                unsigned long long bk = ord64(best);
                #pragma unroll
                for (int off = 16; off; off >>= 1) {
                    unsigned long long ok = __shfl_xor_sync(0xFFFFFFFFu, bk,    off);
                    int                oj = __shfl_xor_sync(0xFFFFFFFFu, bestj, off);
                    if (ok < bk || (ok == bk && oj < bestj)) { bk = ok; bestj = oj; }
                }
                if (lane == 0) { wkey[par][wid] = bk; wjj[par][wid] = bestj; }
                __syncthreads();   // the ONLY barrier in the step

                // stage 2: every warp reduces the 16 partials redundantly
                unsigned long long gk = wkey[par][lane & 15];
                int                gj = wjj[par][lane & 15];
                #pragma unroll
                for (int off = 8; off; off >>= 1) {
                    unsigned long long ok = __shfl_xor_sync(0xFFFFFFFFu, gk, off);
                    int                oj = __shfl_xor_sync(0xFFFFFFFFu, gj, off);
                    if (ok < gk || (ok == gk && oj < gj)) { gk = ok; gj = oj; }
                }
                minVal = unord64(gk);
                const int j1 = gj;
                par ^= 1;

                const int pmatch = p[j1];
                if (pmatch == FREEROW) { jend = j1; break; }

                { int c = j1 - 1; if ((c & (NT - 1)) == tid) usedmask |= 1u << (c >> LOGNT); }
                i0 = pmatch;
                j0 = j1;
            }

            // flush register 'way' to smem for scanned columns + jend only
            #pragma unroll
            for (int t = 0; t < CPT; t++) {
                if ((usedmask >> t) & 1u)
                    way[tid + t * NT + 1] = (unsigned short)wreg[t];
            }
            { int c = jend - 1;
              if ((c & (NT - 1)) == tid) way[jend] = (unsigned short)wreg[c >> LOGNT]; }

            // phase-end dual updates (scanned set only), BEFORE augmentation
            #pragma unroll
            for (int t = 0; t < CPT; t++) {
                if ((usedmask >> t) & 1u) {
                    double adj = minVal - d[t];
                    v[t] -= adj;
                    int j = tid + t * NT + 1;
                    u[p[j]] += adj;              // distinct rows across scanned cols
                }
            }
            if (tid == 0) u[i] += minVal;
            __syncthreads();

            if (tid == 0) {                      // augment along predecessor chain
                int j = jend;
                while (true) {
                    int jp = way[j];
                    if (jp == 0) { p[j] = i; break; }
                    p[j] = p[jp];
                    j = jp;
                }
            }
            __syncthreads();
        }
    }

    // ---- outputs: [0] per_prop_gt_inds, [1] proposal_matched_mask ----
    float* outInds = out + (size_t)b * M;
    float* outMask = out + (size_t)BATCH * M + (size_t)b * M;
    #pragma unroll
    for (int t = 0; t < CPT; t++) {
        int c = tid + t * NT;
        int r = p[c + 1];
        bool matched = (r != FREEROW);
        outInds[c] = matched ? (float)(r - 1) : 0.0f;
        outMask[c] = matched ? 1.0f : 0.0f;
    }
}

extern "C" void kernel_launch(void* const* d_in, const int* in_sizes, int n_in,
                              void* d_out, int out_size) {
    // metadata order: cls_prob[0], gt_box_present[1], num_actual_gt[2],
    //                 gt_normal_normalized[3], query_normals[4]
    const int*   nag = (const int*)  d_in[2];
    const float* gtn = (const float*)d_in[3];
    const float* qn  = (const float*)d_in[4];
    dim3 g1(BATCH, NTILES);
    rowmin_kernel<<<g1, K1NT>>>(nag, gtn, qn);
    assign_kernel<<<BATCH, NT>>>(nag, gtn, qn, (float*)d_out);
}